// round 15
// baseline (speedup 1.0000x reference)
#include <cuda_runtime.h>
#include <cuda_fp16.h>
#include <math.h>
#include <stdint.h>

#define BB 4
#define SS 2048
#define DD 768
#define HH 8
#define DHH 96
#define HID 3072
#define BS (BB*SS)          // 8192
// 1/sqrt(96) * log2(e): softmax runs in exp2 domain
#define SCALE_Q 0.14724494951805885f

// ---------------- scratch (device globals; no allocation) ----------------
__device__ __half g_xn  [(size_t)BS * DD];
__device__ __half g_qkv [(size_t)BS * 3 * DD];
__device__ __half g_attn[(size_t)BS * DD];
__device__ float  g_x1  [(size_t)BS * DD];
__device__ __half g_y   [(size_t)BS * DD];
__device__ __half g_h   [(size_t)BS * HID];
__device__ __half g_qkvw16[(size_t)DD * (3*DD)];
__device__ __half g_projw16[(size_t)DD * DD];
__device__ __half g_fc1w16 [(size_t)DD * HID];
__device__ __half g_fc2w16 [(size_t)HID * DD];

// 10000^(-j/16) for j = 0..15
__constant__ float ROPE_IF[16] = {
    1.0000000000f, 0.5623413252f, 0.3162277660f, 0.1778279410f,
    0.1000000000f, 0.0562341325f, 0.0316227766f, 0.0177827941f,
    0.0100000000f, 0.0056234133f, 0.0031622777f, 0.0017782794f,
    0.0010000000f, 0.0005623413f, 0.0003162278f, 0.0001778279f
};

// ---------------- helpers ---------------------------------------------------
__device__ __forceinline__ void cp_async16(uint32_t dst, const void* src) {
    asm volatile("cp.async.cg.shared.global [%0], [%1], 16;" :: "r"(dst), "l"(src));
}
__device__ __forceinline__ void cp_commit() { asm volatile("cp.async.commit_group;" ::: "memory"); }
__device__ __forceinline__ uint32_t smem_u32(const void* p) {
    uint32_t a;
    asm("{ .reg .u64 t; cvta.to.shared.u64 t, %1; cvt.u32.u64 %0, t; }" : "=r"(a) : "l"(p));
    return a;
}
__device__ __forceinline__ void ldm_x4(uint32_t* r, uint32_t addr) {
    asm volatile("ldmatrix.sync.aligned.m8n8.x4.shared.b16 {%0,%1,%2,%3}, [%4];"
        : "=r"(r[0]), "=r"(r[1]), "=r"(r[2]), "=r"(r[3]) : "r"(addr));
}
__device__ __forceinline__ void ldm_x4t(uint32_t* r, uint32_t addr) {
    asm volatile("ldmatrix.sync.aligned.m8n8.x4.trans.shared.b16 {%0,%1,%2,%3}, [%4];"
        : "=r"(r[0]), "=r"(r[1]), "=r"(r[2]), "=r"(r[3]) : "r"(addr));
}
__device__ __forceinline__ void mma16816(float* c, const uint32_t* a, const uint32_t* b) {
    asm volatile(
        "mma.sync.aligned.m16n8k16.row.col.f32.f16.f16.f32 "
        "{%0,%1,%2,%3}, {%4,%5,%6,%7}, {%8,%9}, {%0,%1,%2,%3};"
        : "+f"(c[0]), "+f"(c[1]), "+f"(c[2]), "+f"(c[3])
        : "r"(a[0]), "r"(a[1]), "r"(a[2]), "r"(a[3]), "r"(b[0]), "r"(b[1]));
}
__device__ __forceinline__ float gelu_fast(float x) {
    float z = 0.7978845608028654f * (x + 0.044715f * x * x * x);
    float t;
    asm("tanh.approx.f32 %0, %1;" : "=f"(t) : "f"(z));
    return 0.5f * x * (1.0f + t);
}

// ---------------- merged: weight convert + LN1 ------------------------------
#define NW1 (DD*(3*DD)/4)
#define NW2 (DD*DD/4)
#define NW3 (DD*HID/4)
#define NW4 (HID*DD/4)
#define NCONV ((NW1 + NW2 + NW3 + NW4) / 256)
__global__ __launch_bounds__(256) void conv_ln(const float* __restrict__ w1,
                                               const float* __restrict__ w2,
                                               const float* __restrict__ w3,
                                               const float* __restrict__ w4,
                                               const float* __restrict__ x,
                                               const float* __restrict__ g,
                                               const float* __restrict__ b,
                                               __half* __restrict__ out) {
    int blk = blockIdx.x;
    int t = threadIdx.x;
    if (blk < NCONV) {
        int i = blk * 256 + t;
        const float* src; __half* dst; int off;
        if (i < NW1)                  { src = w1; dst = g_qkvw16;  off = i; }
        else if (i < NW1 + NW2)       { src = w2; dst = g_projw16; off = i - NW1; }
        else if (i < NW1 + NW2 + NW3) { src = w3; dst = g_fc1w16;  off = i - NW1 - NW2; }
        else                          { src = w4; dst = g_fc2w16;  off = i - NW1 - NW2 - NW3; }
        float4 v = ((const float4*)src)[off];
        __half2 h0 = __floats2half2_rn(v.x, v.y);
        __half2 h1 = __floats2half2_rn(v.z, v.w);
        ((__half2*)dst)[off * 2]     = h0;
        ((__half2*)dst)[off * 2 + 1] = h1;
        return;
    }
    int row = blk - NCONV;
    const float* xr = x + (size_t)row * DD;
    float v0 = xr[t], v1 = xr[t + 256], v2 = xr[t + 512];
    float s  = v0 + v1 + v2;
    float ss = v0*v0 + v1*v1 + v2*v2;
    #pragma unroll
    for (int o = 16; o > 0; o >>= 1) {
        s  += __shfl_xor_sync(0xffffffffu, s,  o);
        ss += __shfl_xor_sync(0xffffffffu, ss, o);
    }
    __shared__ float rs[8], rss[8];
    if ((t & 31) == 0) { rs[t >> 5] = s; rss[t >> 5] = ss; }
    __syncthreads();
    float S1 = 0.f, S2 = 0.f;
    #pragma unroll
    for (int i = 0; i < 8; i++) { S1 += rs[i]; S2 += rss[i]; }
    float mean = S1 * (1.0f / DD);
    float var  = S2 * (1.0f / DD) - mean * mean;
    float rstd = rsqrtf(var + 1e-6f);
    __half* orow = out + (size_t)row * DD;
    orow[t      ] = __float2half_rn((v0 - mean) * rstd * g[t      ] + b[t      ]);
    orow[t + 256] = __float2half_rn((v1 - mean) * rstd * g[t + 256] + b[t + 256]);
    orow[t + 512] = __float2half_rn((v2 - mean) * rstd * g[t + 512] + b[t + 512]);
}

// ---------------- LayerNorm (standalone, LN2) --------------------------------
__global__ __launch_bounds__(256) void ln_kernel(const float* __restrict__ x,
                                                 const float* __restrict__ g,
                                                 const float* __restrict__ b,
                                                 __half* __restrict__ out) {
    int row = blockIdx.x;
    int t = threadIdx.x;
    const float* xr = x + (size_t)row * DD;
    float v0 = xr[t], v1 = xr[t + 256], v2 = xr[t + 512];
    float s  = v0 + v1 + v2;
    float ss = v0*v0 + v1*v1 + v2*v2;
    #pragma unroll
    for (int o = 16; o > 0; o >>= 1) {
        s  += __shfl_xor_sync(0xffffffffu, s,  o);
        ss += __shfl_xor_sync(0xffffffffu, ss, o);
    }
    __shared__ float rs[8], rss[8];
    if ((t & 31) == 0) { rs[t >> 5] = s; rss[t >> 5] = ss; }
    __syncthreads();
    float S1 = 0.f, S2 = 0.f;
    #pragma unroll
    for (int i = 0; i < 8; i++) { S1 += rs[i]; S2 += rss[i]; }
    float mean = S1 * (1.0f / DD);
    float var  = S2 * (1.0f / DD) - mean * mean;
    float rstd = rsqrtf(var + 1e-6f);
    __half* orow = out + (size_t)row * DD;
    orow[t      ] = __float2half_rn((v0 - mean) * rstd * g[t      ] + b[t      ]);
    orow[t + 256] = __float2half_rn((v1 - mean) * rstd * g[t + 256] + b[t + 256]);
    orow[t + 512] = __float2half_rn((v2 - mean) * rstd * g[t + 512] + b[t + 512]);
}

// ---------------- fp16 mma GEMM, B row-major [K,N] via ldmatrix.trans -------
// CTA 128x128, 256 threads (8 warps of 32x64), K-chunk 64, 3-stage cp.async.
// modes: 0 plain fp16; 1 GELU fp16; 2 +res fp32; 3 fused RoPE (QKV)
__global__ __launch_bounds__(256, 2) void gemm_fp16(const __half* __restrict__ A,
                                                    const __half* __restrict__ W,
                                                    const float* __restrict__ bias,
                                                    const float* __restrict__ res,
                                                    float* __restrict__ Cf,
                                                    __half* __restrict__ Ch,
                                                    const float* __restrict__ coords,
                                                    int M, int N, int K, int mode) {
    extern __shared__ char smem[];
    uint32_t sbase = smem_u32(smem);
    const int tid = threadIdx.x, lane = tid & 31, w = tid >> 5;
    const int m0 = blockIdx.y * 128, n0 = blockIdx.x * 128;

    const int ar = tid >> 1, ac = (tid & 1) * 4;
    const __half* aP = A + (size_t)(m0 + ar) * K + ac * 8;
    uint32_t aoff[4];
    #pragma unroll
    for (int j = 0; j < 4; j++)
        aoff[j] = (uint32_t)ar * 128u + (uint32_t)(((ac + j) ^ (ar & 7)) << 4);
    const int br = tid >> 2, bc = (tid & 3) * 4;
    const __half* bP = W + (size_t)br * N + n0 + bc * 8;
    uint32_t boff[4];
    #pragma unroll
    for (int j = 0; j < 4; j++) {
        int c = bc + j;
        boff[j] = (uint32_t)br * 256u + (uint32_t)(((c & 8) | ((c ^ br) & 7)) << 4);
    }

    const int NC = K / 64;

    float acc[2][8][4];
    #pragma unroll
    for (int mt = 0; mt < 2; mt++)
        #pragma unroll
        for (int nt = 0; nt < 8; nt++)
            #pragma unroll
            for (int i = 0; i < 4; i++) acc[mt][nt][i] = 0.f;

    const int L = lane & 7, gb = (lane >> 3) & 1, gh = lane >> 4;
    const int wm = (w >> 1) * 32, wn = (w & 1) * 64;
    uint32_t aRow[2];
    #pragma unroll
    for (int mt = 0; mt < 2; mt++) aRow[mt] = (uint32_t)(wm + mt * 16 + gb * 8 + L) * 128u;

    #pragma unroll
    for (int pre = 0; pre < 2; pre++) {
        if (pre < NC) {
            uint32_t sa = sbase + (uint32_t)pre * 32768u;
            uint32_t sb = sa + 16384;
            const __half* ap = aP + (size_t)pre * 64;
            const __half* bp = bP + (size_t)pre * 64 * N;
            #pragma unroll
            for (int j = 0; j < 4; j++) {
                cp_async16(sa + aoff[j], ap + j * 8);
                cp_async16(sb + boff[j], bp + j * 8);
            }
            cp_commit();
        }
    }

    for (int ch = 0; ch < NC; ch++) {
        if (ch < NC - 1) { asm volatile("cp.async.wait_group 1;" ::: "memory"); }
        else             { asm volatile("cp.async.wait_group 0;" ::: "memory"); }
        __syncthreads();

        if (ch + 2 < NC) {
            uint32_t na = sbase + (uint32_t)((ch + 2) % 3) * 32768u;
            uint32_t nb = na + 16384;
            const __half* ap = aP + (size_t)(ch + 2) * 64;
            const __half* bp = bP + (size_t)(ch + 2) * 64 * N;
            #pragma unroll
            for (int j = 0; j < 4; j++) {
                cp_async16(na + aoff[j], ap + j * 8);
                cp_async16(nb + boff[j], bp + j * 8);
            }
            cp_commit();
        }

        uint32_t stA = sbase + (uint32_t)(ch % 3) * 32768u;
        uint32_t stB = stA + 16384;

        #pragma unroll
        for (int ks = 0; ks < 4; ks++) {
            uint32_t af[2][4];
            #pragma unroll
            for (int mt = 0; mt < 2; mt++)
                ldm_x4(af[mt], stA + aRow[mt] + ((uint32_t)((2 * ks + gh) ^ L) << 4));
            int krow = ks * 16 + L + gb * 8;
            uint32_t rb = stB + (uint32_t)krow * 256u;
            uint32_t bf[4][4];
            #pragma unroll
            for (int p = 0; p < 4; p++) {
                int c = (wn >> 3) + 2 * p + gh;
                ldm_x4t(bf[p], rb + ((uint32_t)((c & 8) | ((c ^ L) & 7)) << 4));
            }
            #pragma unroll
            for (int mt = 0; mt < 2; mt++)
                #pragma unroll
                for (int p = 0; p < 4; p++) {
                    mma16816(acc[mt][2 * p],     af[mt], bf[p]);
                    mma16816(acc[mt][2 * p + 1], af[mt], bf[p] + 2);
                }
        }
    }

    // ---------------- epilogue ----------------
    const int lane4 = lane >> 2, u = lane & 3;
    if (mode == 3) {
        #pragma unroll
        for (int mt = 0; mt < 2; mt++) {
            #pragma unroll
            for (int hf = 0; hf < 2; hf++) {
                int m = m0 + wm + mt * 16 + lane4 + hf * 8;
                const float* cr = coords + (size_t)m * 3;
                __half* crow = Ch + (size_t)m * N;
                #pragma unroll
                for (int bi = 0; bi < 2; bi++) {
                    int colblk = n0 + wn + bi * 32;
                    int part = colblk / DD;          // 0=q,1=k,2=v
                    if (part == 2) {
                        #pragma unroll
                        for (int pp = 0; pp < 4; pp++) {
                            int nt = bi * 4 + pp;
                            int n = n0 + wn + nt * 8 + 2 * u;
                            float c0 = acc[mt][nt][hf * 2    ] + bias[n];
                            float c1 = acc[mt][nt][hf * 2 + 1] + bias[n + 1];
                            *(__half2*)(crow + n) = __floats2half2_rn(c0, c1);
                        }
                    } else {
                        int axis = (colblk % DHH) >> 5;
                        float coord = cr[axis];
                        float sc = (part == 0) ? SCALE_Q : 1.0f;
                        #pragma unroll
                        for (int pp = 0; pp < 2; pp++) {
                            int nt1 = bi * 4 + pp, nt2 = nt1 + 2;
                            int n1 = n0 + wn + nt1 * 8 + 2 * u;
                            int n2 = n1 + 16;
                            int j0 = pp * 8 + 2 * u;
                            float ang0 = coord * ROPE_IF[j0];
                            float ang1 = coord * ROPE_IF[j0 + 1];
                            float sn0, cs0, sn1, cs1;
                            __sincosf(ang0, &sn0, &cs0);
                            __sincosf(ang1, &sn1, &cs1);
                            float x10 = acc[mt][nt1][hf * 2    ] + bias[n1];
                            float x11 = acc[mt][nt1][hf * 2 + 1] + bias[n1 + 1];
                            float x20 = acc[mt][nt2][hf * 2    ] + bias[n2];
                            float x21 = acc[mt][nt2][hf * 2 + 1] + bias[n2 + 1];
                            *(__half2*)(crow + n1) = __floats2half2_rn(
                                sc * (x10 * cs0 - x20 * sn0), sc * (x11 * cs1 - x21 * sn1));
                            *(__half2*)(crow + n2) = __floats2half2_rn(
                                sc * (x10 * sn0 + x20 * cs0), sc * (x11 * sn1 + x21 * cs1));
                        }
                    }
                }
            }
        }
    } else {
        #pragma unroll
        for (int mt = 0; mt < 2; mt++) {
            #pragma unroll
            for (int hf = 0; hf < 2; hf++) {
                int m = m0 + wm + mt * 16 + lane4 + hf * 8;
                #pragma unroll
                for (int nt = 0; nt < 8; nt++) {
                    int n = n0 + wn + nt * 8 + 2 * u;
                    float c0 = acc[mt][nt][hf * 2    ] + bias[n];
                    float c1 = acc[mt][nt][hf * 2 + 1] + bias[n + 1];
                    if (mode == 2) {
                        const float* rrow = res + (size_t)m * N;
                        float2 o;
                        o.x = c0 + rrow[n];
                        o.y = c1 + rrow[n + 1];
                        *(float2*)(Cf + (size_t)m * N + n) = o;   // STG.64
                    } else {
                        if (mode == 1) {
                            c0 = gelu_fast(c0);
                            c1 = gelu_fast(c1);
                        }
                        *(__half2*)(Ch + (size_t)m * N + n) = __floats2half2_rn(c0, c1);
                    }
                }
            }
        }
    }
}

// ---------------- fp16 tensor-core causal flash attention -------------------
// 64 q-rows/block, 128 threads, kv tiles of 64, double-buffered K/V,
// exp2-domain softmax, ONE barrier per tile, conditional rescale,
// diagonal-tile MMA skipping (warp-uniform: p<=w for S, j<=w for PV).
__global__ __launch_bounds__(128) void attn_fp16() {
    extern __shared__ char sm[];
    const uint32_t base = smem_u32(sm);
    const int t = threadIdx.x, lane = t & 31, w = t >> 5;
    const int L = lane & 7, gb = (lane >> 3) & 1, gh = lane >> 4;
    const int lane4 = lane >> 2, u = lane & 3;
    const int qt = blockIdx.x;
    const int bh = blockIdx.y;
    const int b = bh >> 3, h = bh & 7;
    const __half* qkv = g_qkv + (size_t)b * SS * (3 * DD);

    uint32_t soff[6]; int rows[6], cks[6];
    #pragma unroll
    for (int it = 0; it < 6; it++) {
        int idx = t + 128 * it;
        int row = idx / 12, c = idx % 12;
        rows[it] = row; cks[it] = c;
        soff[it] = (uint32_t)row * 256u + ((uint32_t)((c & 8) | ((c ^ row) & 7)) << 4);
    }

    #pragma unroll
    for (int it = 0; it < 6; it++)
        cp_async16(base + soff[it], qkv + (size_t)(qt * 64 + rows[it]) * (3 * DD) + h * DHH + cks[it] * 8);
    cp_commit();
    asm volatile("cp.async.wait_group 0;" ::: "memory");
    __syncthreads();

    uint32_t qa[6][4];
    const uint32_t qRow = (uint32_t)(w * 16 + gb * 8 + L) * 256u;
    #pragma unroll
    for (int ks = 0; ks < 6; ks++) {
        int c = 2 * ks + gh;
        ldm_x4(qa[ks], base + qRow + ((uint32_t)((c & 8) | ((c ^ L) & 7)) << 4));
    }
    __syncthreads();

    float oacc[12][4];
    #pragma unroll
    for (int nt = 0; nt < 12; nt++)
        #pragma unroll
        for (int i = 0; i < 4; i++) oacc[nt][i] = 0.f;
    float m0 = -INFINITY, m1 = -INFINITY, l0 = 0.f, l1 = 0.f;

    uint32_t kRow[4];
    #pragma unroll
    for (int p = 0; p < 4; p++) kRow[p] = (uint32_t)(p * 16 + gh * 8 + L) * 256u;

    #pragma unroll
    for (int it = 0; it < 6; it++) {
        const __half* kp = qkv + (size_t)rows[it] * (3 * DD) + DD + h * DHH + cks[it] * 8;
        cp_async16(base + soff[it], kp);
        cp_async16(base + 32768u + soff[it], kp + DD);
    }
    cp_commit();

    for (int kt = 0; kt <= qt; kt++) {
        uint32_t buf = (uint32_t)(kt & 1) * 16384u;
        asm volatile("cp.async.wait_group 0;" ::: "memory");
        __syncthreads();

        if (kt < qt) {
            uint32_t nbuf = (uint32_t)((kt + 1) & 1) * 16384u;
            #pragma unroll
            for (int it = 0; it < 6; it++) {
                const __half* kp = qkv + (size_t)((kt + 1) * 64 + rows[it]) * (3 * DD) + DD + h * DHH + cks[it] * 8;
                cp_async16(base + nbuf + soff[it], kp);
                cp_async16(base + 32768u + nbuf + soff[it], kp + DD);
            }
            cp_commit();
        }

        const uint32_t kb = base + buf;
        const uint32_t vb = base + 32768u + buf;
        const bool diag = (kt == qt);

        float sfr[8][4];
        #pragma unroll
        for (int nt = 0; nt < 8; nt++)
            #pragma unroll
            for (int i = 0; i < 4; i++) sfr[nt][i] = 0.f;
        #pragma unroll
        for (int ks = 0; ks < 6; ks++) {
            int c = 2 * ks + gb;
            uint32_t coff = (uint32_t)((c & 8) | ((c ^ L) & 7)) << 4;
            #pragma unroll
            for (int p = 0; p < 4; p++) {
                // diagonal tile: warp w (rows <= w*16+15) needs kv cols <= 16p+15
                // only when p <= w. Warp-uniform skip.
                if (diag && p > w) continue;
                uint32_t bf[4];
                ldm_x4(bf, kb + kRow[p] + coff);
                mma16816(sfr[2 * p],     qa[ks], bf);
                mma16816(sfr[2 * p + 1], qa[ks], bf + 2);
            }
        }
        if (diag) {
            int r0 = w * 16 + lane4, r1 = r0 + 8;
            #pragma unroll
            for (int nt = 0; nt < 8; nt++) {
                int ca = nt * 8 + 2 * u, cbn = ca + 1;
                if (ca  > r0) sfr[nt][0] = -1e30f;
                if (cbn > r0) sfr[nt][1] = -1e30f;
                if (ca  > r1) sfr[nt][2] = -1e30f;
                if (cbn > r1) sfr[nt][3] = -1e30f;
            }
        }
        float mx0 = -INFINITY, mx1 = -INFINITY;
        #pragma unroll
        for (int nt = 0; nt < 8; nt++) {
            mx0 = fmaxf(mx0, fmaxf(sfr[nt][0], sfr[nt][1]));
            mx1 = fmaxf(mx1, fmaxf(sfr[nt][2], sfr[nt][3]));
        }
        mx0 = fmaxf(mx0, __shfl_xor_sync(0xffffffffu, mx0, 1));
        mx0 = fmaxf(mx0, __shfl_xor_sync(0xffffffffu, mx0, 2));
        mx1 = fmaxf(mx1, __shfl_xor_sync(0xffffffffu, mx1, 1));
        mx1 = fmaxf(mx1, __shfl_xor_sync(0xffffffffu, mx1, 2));
        float mn0 = fmaxf(m0, mx0), mn1 = fmaxf(m1, mx1);
        if (mn0 > m0 || mn1 > m1) {
            float al0 = exp2f(m0 - mn0), al1 = exp2f(m1 - mn1);
            m0 = mn0; m1 = mn1;
            l0 *= al0; l1 *= al1;
            #pragma unroll
            for (int nt = 0; nt < 12; nt++) {
                oacc[nt][0] *= al0; oacc[nt][1] *= al0;
                oacc[nt][2] *= al1; oacc[nt][3] *= al1;
            }
        }
        #pragma unroll
        for (int nt = 0; nt < 8; nt++) {
            float p0 = exp2f(sfr[nt][0] - m0), p1 = exp2f(sfr[nt][1] - m0);
            float p2 = exp2f(sfr[nt][2] - m1), p3 = exp2f(sfr[nt][3] - m1);
            l0 += p0 + p1; l1 += p2 + p3;
            sfr[nt][0] = p0; sfr[nt][1] = p1; sfr[nt][2] = p2; sfr[nt][3] = p3;
        }
        #pragma unroll
        for (int j = 0; j < 4; j++) {
            // diagonal tile: P columns (kv) j*16.. are all zero for j > w.
            if (diag && j > w) continue;
            uint32_t a[4];
            __half2 h0 = __floats2half2_rn(sfr[2*j][0],     sfr[2*j][1]);
            __half2 h1 = __floats2half2_rn(sfr[2*j][2],     sfr[2*j][3]);
            __half2 h2 = __floats2half2_rn(sfr[2*j + 1][0], sfr[2*j + 1][1]);
            __half2 h3 = __floats2half2_rn(sfr[2*j + 1][2], sfr[2*j + 1][3]);
            a[0] = *(uint32_t*)&h0; a[1] = *(uint32_t*)&h1;
            a[2] = *(uint32_t*)&h2; a[3] = *(uint32_t*)&h3;
            uint32_t rv = vb + (uint32_t)(j * 16 + L + gb * 8) * 256u;
            #pragma unroll
            for (int p = 0; p < 6; p++) {
                int c = 2 * p + gh;
                uint32_t bf[4];
                ldm_x4t(bf, rv + ((uint32_t)((c & 8) | ((c ^ L) & 7)) << 4));
                mma16816(oacc[2 * p],     a, bf);
                mma16816(oacc[2 * p + 1], a, bf + 2);
            }
        }
    }

    l0 += __shfl_xor_sync(0xffffffffu, l0, 1);
    l0 += __shfl_xor_sync(0xffffffffu, l0, 2);
    l1 += __shfl_xor_sync(0xffffffffu, l1, 1);
    l1 += __shfl_xor_sync(0xffffffffu, l1, 2);
    float i0 = 1.0f / l0, i1 = 1.0f / l1;
    int gr0 = qt * 64 + w * 16 + lane4, gr1 = gr0 + 8;
    __half* o0 = g_attn + (size_t)(b * SS + gr0) * DD + h * DHH;
    __half* o1 = g_attn + (size_t)(b * SS + gr1) * DD + h * DHH;
    #pragma unroll
    for (int nt = 0; nt < 12; nt++) {
        int c = nt * 8 + 2 * u;
        __half2 a0 = __floats2half2_rn(oacc[nt][0] * i0, oacc[nt][1] * i0);
        __half2 a1 = __floats2half2_rn(oacc[nt][2] * i1, oacc[nt][3] * i1);
        *(__half2*)(o0 + c) = a0;
        *(__half2*)(o1 + c) = a1;
    }
}

// ---------------- launch ----------------------------------------------------
extern "C" void kernel_launch(void* const* d_in, const int* in_sizes, int n_in,
                              void* d_out, int out_size) {
    const float* src     = (const float*)d_in[0];
    const float* coords  = (const float*)d_in[1];
    const float* norm1_g = (const float*)d_in[3];
    const float* norm1_b = (const float*)d_in[4];
    const float* qkv_w   = (const float*)d_in[5];
    const float* qkv_b   = (const float*)d_in[6];
    const float* proj_w  = (const float*)d_in[7];
    const float* proj_b  = (const float*)d_in[8];
    const float* norm2_g = (const float*)d_in[9];
    const float* norm2_b = (const float*)d_in[10];
    const float* fc1_w   = (const float*)d_in[11];
    const float* fc1_b   = (const float*)d_in[12];
    const float* fc2_w   = (const float*)d_in[13];
    const float* fc2_b   = (const float*)d_in[14];
    float* out = (float*)d_out;

    __half *xn, *qkvp, *attnp, *yp, *hp;
    __half *qkvw, *projw, *fc1w, *fc2w;
    float *x1p;
    cudaGetSymbolAddress((void**)&xn,    g_xn);
    cudaGetSymbolAddress((void**)&qkvp,  g_qkv);
    cudaGetSymbolAddress((void**)&attnp, g_attn);
    cudaGetSymbolAddress((void**)&x1p,   g_x1);
    cudaGetSymbolAddress((void**)&yp,    g_y);
    cudaGetSymbolAddress((void**)&hp,    g_h);
    cudaGetSymbolAddress((void**)&qkvw,  g_qkvw16);
    cudaGetSymbolAddress((void**)&projw, g_projw16);
    cudaGetSymbolAddress((void**)&fc1w,  g_fc1w16);
    cudaGetSymbolAddress((void**)&fc2w,  g_fc2w16);

    static bool attr_set = false;
    if (!attr_set) {
        cudaFuncSetAttribute(gemm_fp16, cudaFuncAttributeMaxDynamicSharedMemorySize, 98304);
        cudaFuncSetAttribute(attn_fp16, cudaFuncAttributeMaxDynamicSharedMemorySize, 65536);
        attr_set = true;
    }

    conv_ln<<<NCONV + BS, 256>>>(qkv_w, proj_w, fc1_w, fc2_w,
                                 src, norm1_g, norm1_b, xn);
    gemm_fp16<<<dim3((3*DD)/128, BS/128), 256, 98304>>>(
        xn, qkvw, qkv_b, nullptr, nullptr, qkvp, coords, BS, 3*DD, DD, 3);
    attn_fp16<<<dim3(SS / 64, BB * HH), 128, 65536>>>();
    gemm_fp16<<<dim3(DD/128, BS/128), 256, 98304>>>(
        attnp, projw, proj_b, src, x1p, nullptr, nullptr, BS, DD, DD, 2);
    ln_kernel<<<BS, 256>>>(x1p, norm2_g, norm2_b, yp);
    gemm_fp16<<<dim3(HID/128, BS/128), 256, 98304>>>(
        yp, fc1w, fc1_b, nullptr, nullptr, hp, nullptr, BS, HID, DD, 1);
    gemm_fp16<<<dim3(DD/128, BS/128), 256, 98304>>>(
        hp, fc2w, fc2_b, x1p, out, nullptr, nullptr, BS, DD, HID, 2);
}

// round 16
// speedup vs baseline: 1.0357x; 1.0357x over previous
#include <cuda_runtime.h>
#include <cuda_fp16.h>
#include <math.h>
#include <stdint.h>

#define BB 4
#define SS 2048
#define DD 768
#define HH 8
#define DHH 96
#define HID 3072
#define BS (BB*SS)          // 8192
// 1/sqrt(96) * log2(e): softmax runs in exp2 domain
#define SCALE_Q 0.14724494951805885f

// ---------------- scratch (device globals; no allocation) ----------------
__device__ __half g_xn  [(size_t)BS * DD];
__device__ __half g_qkv [(size_t)BS * 3 * DD];
__device__ __half g_attn[(size_t)BS * DD];
__device__ float  g_x1  [(size_t)BS * DD];
__device__ __half g_y   [(size_t)BS * DD];
__device__ __half g_h   [(size_t)BS * HID];
__device__ __half g_qkvw16[(size_t)DD * (3*DD)];
__device__ __half g_projw16[(size_t)DD * DD];
__device__ __half g_fc1w16 [(size_t)DD * HID];
__device__ __half g_fc2w16 [(size_t)HID * DD];

// 10000^(-j/16) for j = 0..15
__constant__ float ROPE_IF[16] = {
    1.0000000000f, 0.5623413252f, 0.3162277660f, 0.1778279410f,
    0.1000000000f, 0.0562341325f, 0.0316227766f, 0.0177827941f,
    0.0100000000f, 0.0056234133f, 0.0031622777f, 0.0017782794f,
    0.0010000000f, 0.0005623413f, 0.0003162278f, 0.0001778279f
};

// ---------------- helpers ---------------------------------------------------
__device__ __forceinline__ void cp_async16(uint32_t dst, const void* src) {
    asm volatile("cp.async.cg.shared.global [%0], [%1], 16;" :: "r"(dst), "l"(src));
}
__device__ __forceinline__ void cp_commit() { asm volatile("cp.async.commit_group;" ::: "memory"); }
__device__ __forceinline__ uint32_t smem_u32(const void* p) {
    uint32_t a;
    asm("{ .reg .u64 t; cvta.to.shared.u64 t, %1; cvt.u32.u64 %0, t; }" : "=r"(a) : "l"(p));
    return a;
}
__device__ __forceinline__ void ldm_x4(uint32_t* r, uint32_t addr) {
    asm volatile("ldmatrix.sync.aligned.m8n8.x4.shared.b16 {%0,%1,%2,%3}, [%4];"
        : "=r"(r[0]), "=r"(r[1]), "=r"(r[2]), "=r"(r[3]) : "r"(addr));
}
__device__ __forceinline__ void ldm_x4t(uint32_t* r, uint32_t addr) {
    asm volatile("ldmatrix.sync.aligned.m8n8.x4.trans.shared.b16 {%0,%1,%2,%3}, [%4];"
        : "=r"(r[0]), "=r"(r[1]), "=r"(r[2]), "=r"(r[3]) : "r"(addr));
}
__device__ __forceinline__ void mma16816(float* c, const uint32_t* a, const uint32_t* b) {
    asm volatile(
        "mma.sync.aligned.m16n8k16.row.col.f32.f16.f16.f32 "
        "{%0,%1,%2,%3}, {%4,%5,%6,%7}, {%8,%9}, {%0,%1,%2,%3};"
        : "+f"(c[0]), "+f"(c[1]), "+f"(c[2]), "+f"(c[3])
        : "r"(a[0]), "r"(a[1]), "r"(a[2]), "r"(a[3]), "r"(b[0]), "r"(b[1]));
}
__device__ __forceinline__ float gelu_fast(float x) {
    float z = 0.7978845608028654f * (x + 0.044715f * x * x * x);
    float t;
    asm("tanh.approx.f32 %0, %1;" : "=f"(t) : "f"(z));
    return 0.5f * x * (1.0f + t);
}

// ---------------- merged: weight convert + LN1 ------------------------------
#define NW1 (DD*(3*DD)/4)
#define NW2 (DD*DD/4)
#define NW3 (DD*HID/4)
#define NW4 (HID*DD/4)
#define NCONV ((NW1 + NW2 + NW3 + NW4) / 256)
__global__ __launch_bounds__(256) void conv_ln(const float* __restrict__ w1,
                                               const float* __restrict__ w2,
                                               const float* __restrict__ w3,
                                               const float* __restrict__ w4,
                                               const float* __restrict__ x,
                                               const float* __restrict__ g,
                                               const float* __restrict__ b,
                                               __half* __restrict__ out) {
    int blk = blockIdx.x;
    int t = threadIdx.x;
    if (blk < NCONV) {
        int i = blk * 256 + t;
        const float* src; __half* dst; int off;
        if (i < NW1)                  { src = w1; dst = g_qkvw16;  off = i; }
        else if (i < NW1 + NW2)       { src = w2; dst = g_projw16; off = i - NW1; }
        else if (i < NW1 + NW2 + NW3) { src = w3; dst = g_fc1w16;  off = i - NW1 - NW2; }
        else                          { src = w4; dst = g_fc2w16;  off = i - NW1 - NW2 - NW3; }
        float4 v = ((const float4*)src)[off];
        __half2 h0 = __floats2half2_rn(v.x, v.y);
        __half2 h1 = __floats2half2_rn(v.z, v.w);
        ((__half2*)dst)[off * 2]     = h0;
        ((__half2*)dst)[off * 2 + 1] = h1;
        return;
    }
    int row = blk - NCONV;
    const float* xr = x + (size_t)row * DD;
    float v0 = xr[t], v1 = xr[t + 256], v2 = xr[t + 512];
    float s  = v0 + v1 + v2;
    float ss = v0*v0 + v1*v1 + v2*v2;
    #pragma unroll
    for (int o = 16; o > 0; o >>= 1) {
        s  += __shfl_xor_sync(0xffffffffu, s,  o);
        ss += __shfl_xor_sync(0xffffffffu, ss, o);
    }
    __shared__ float rs[8], rss[8];
    if ((t & 31) == 0) { rs[t >> 5] = s; rss[t >> 5] = ss; }
    __syncthreads();
    float S1 = 0.f, S2 = 0.f;
    #pragma unroll
    for (int i = 0; i < 8; i++) { S1 += rs[i]; S2 += rss[i]; }
    float mean = S1 * (1.0f / DD);
    float var  = S2 * (1.0f / DD) - mean * mean;
    float rstd = rsqrtf(var + 1e-6f);
    __half* orow = out + (size_t)row * DD;
    orow[t      ] = __float2half_rn((v0 - mean) * rstd * g[t      ] + b[t      ]);
    orow[t + 256] = __float2half_rn((v1 - mean) * rstd * g[t + 256] + b[t + 256]);
    orow[t + 512] = __float2half_rn((v2 - mean) * rstd * g[t + 512] + b[t + 512]);
}

// ---------------- LayerNorm (standalone, LN2) --------------------------------
__global__ __launch_bounds__(256) void ln_kernel(const float* __restrict__ x,
                                                 const float* __restrict__ g,
                                                 const float* __restrict__ b,
                                                 __half* __restrict__ out) {
    int row = blockIdx.x;
    int t = threadIdx.x;
    const float* xr = x + (size_t)row * DD;
    float v0 = xr[t], v1 = xr[t + 256], v2 = xr[t + 512];
    float s  = v0 + v1 + v2;
    float ss = v0*v0 + v1*v1 + v2*v2;
    #pragma unroll
    for (int o = 16; o > 0; o >>= 1) {
        s  += __shfl_xor_sync(0xffffffffu, s,  o);
        ss += __shfl_xor_sync(0xffffffffu, ss, o);
    }
    __shared__ float rs[8], rss[8];
    if ((t & 31) == 0) { rs[t >> 5] = s; rss[t >> 5] = ss; }
    __syncthreads();
    float S1 = 0.f, S2 = 0.f;
    #pragma unroll
    for (int i = 0; i < 8; i++) { S1 += rs[i]; S2 += rss[i]; }
    float mean = S1 * (1.0f / DD);
    float var  = S2 * (1.0f / DD) - mean * mean;
    float rstd = rsqrtf(var + 1e-6f);
    __half* orow = out + (size_t)row * DD;
    orow[t      ] = __float2half_rn((v0 - mean) * rstd * g[t      ] + b[t      ]);
    orow[t + 256] = __float2half_rn((v1 - mean) * rstd * g[t + 256] + b[t + 256]);
    orow[t + 512] = __float2half_rn((v2 - mean) * rstd * g[t + 512] + b[t + 512]);
}

// ---------------- fp16 mma GEMM, B row-major [K,N] via ldmatrix.trans -------
// CTA 128x128, 256 threads (8 warps of 32x64), K-chunk 64, 3-stage cp.async.
// modes: 0 plain fp16; 1 GELU fp16; 2 +res fp32 (STG.64); 3 fused RoPE (QKV)
__global__ __launch_bounds__(256, 2) void gemm_fp16(const __half* __restrict__ A,
                                                    const __half* __restrict__ W,
                                                    const float* __restrict__ bias,
                                                    const float* __restrict__ res,
                                                    float* __restrict__ Cf,
                                                    __half* __restrict__ Ch,
                                                    const float* __restrict__ coords,
                                                    int M, int N, int K, int mode) {
    extern __shared__ char smem[];
    uint32_t sbase = smem_u32(smem);
    const int tid = threadIdx.x, lane = tid & 31, w = tid >> 5;
    const int m0 = blockIdx.y * 128, n0 = blockIdx.x * 128;

    const int ar = tid >> 1, ac = (tid & 1) * 4;
    const __half* aP = A + (size_t)(m0 + ar) * K + ac * 8;
    uint32_t aoff[4];
    #pragma unroll
    for (int j = 0; j < 4; j++)
        aoff[j] = (uint32_t)ar * 128u + (uint32_t)(((ac + j) ^ (ar & 7)) << 4);
    const int br = tid >> 2, bc = (tid & 3) * 4;
    const __half* bP = W + (size_t)br * N + n0 + bc * 8;
    uint32_t boff[4];
    #pragma unroll
    for (int j = 0; j < 4; j++) {
        int c = bc + j;
        boff[j] = (uint32_t)br * 256u + (uint32_t)(((c & 8) | ((c ^ br) & 7)) << 4);
    }

    const int NC = K / 64;

    float acc[2][8][4];
    #pragma unroll
    for (int mt = 0; mt < 2; mt++)
        #pragma unroll
        for (int nt = 0; nt < 8; nt++)
            #pragma unroll
            for (int i = 0; i < 4; i++) acc[mt][nt][i] = 0.f;

    const int L = lane & 7, gb = (lane >> 3) & 1, gh = lane >> 4;
    const int wm = (w >> 1) * 32, wn = (w & 1) * 64;
    uint32_t aRow[2];
    #pragma unroll
    for (int mt = 0; mt < 2; mt++) aRow[mt] = (uint32_t)(wm + mt * 16 + gb * 8 + L) * 128u;

    #pragma unroll
    for (int pre = 0; pre < 2; pre++) {
        if (pre < NC) {
            uint32_t sa = sbase + (uint32_t)pre * 32768u;
            uint32_t sb = sa + 16384;
            const __half* ap = aP + (size_t)pre * 64;
            const __half* bp = bP + (size_t)pre * 64 * N;
            #pragma unroll
            for (int j = 0; j < 4; j++) {
                cp_async16(sa + aoff[j], ap + j * 8);
                cp_async16(sb + boff[j], bp + j * 8);
            }
            cp_commit();
        }
    }

    for (int ch = 0; ch < NC; ch++) {
        if (ch < NC - 1) { asm volatile("cp.async.wait_group 1;" ::: "memory"); }
        else             { asm volatile("cp.async.wait_group 0;" ::: "memory"); }
        __syncthreads();

        if (ch + 2 < NC) {
            uint32_t na = sbase + (uint32_t)((ch + 2) % 3) * 32768u;
            uint32_t nb = na + 16384;
            const __half* ap = aP + (size_t)(ch + 2) * 64;
            const __half* bp = bP + (size_t)(ch + 2) * 64 * N;
            #pragma unroll
            for (int j = 0; j < 4; j++) {
                cp_async16(na + aoff[j], ap + j * 8);
                cp_async16(nb + boff[j], bp + j * 8);
            }
            cp_commit();
        }

        uint32_t stA = sbase + (uint32_t)(ch % 3) * 32768u;
        uint32_t stB = stA + 16384;

        #pragma unroll
        for (int ks = 0; ks < 4; ks++) {
            uint32_t af[2][4];
            #pragma unroll
            for (int mt = 0; mt < 2; mt++)
                ldm_x4(af[mt], stA + aRow[mt] + ((uint32_t)((2 * ks + gh) ^ L) << 4));
            int krow = ks * 16 + L + gb * 8;
            uint32_t rb = stB + (uint32_t)krow * 256u;
            uint32_t bf[4][4];
            #pragma unroll
            for (int p = 0; p < 4; p++) {
                int c = (wn >> 3) + 2 * p + gh;
                ldm_x4t(bf[p], rb + ((uint32_t)((c & 8) | ((c ^ L) & 7)) << 4));
            }
            #pragma unroll
            for (int mt = 0; mt < 2; mt++)
                #pragma unroll
                for (int p = 0; p < 4; p++) {
                    mma16816(acc[mt][2 * p],     af[mt], bf[p]);
                    mma16816(acc[mt][2 * p + 1], af[mt], bf[p] + 2);
                }
        }
    }

    // ---------------- epilogue ----------------
    const int lane4 = lane >> 2, u = lane & 3;
    if (mode == 3) {
        #pragma unroll
        for (int mt = 0; mt < 2; mt++) {
            #pragma unroll
            for (int hf = 0; hf < 2; hf++) {
                int m = m0 + wm + mt * 16 + lane4 + hf * 8;
                const float* cr = coords + (size_t)m * 3;
                __half* crow = Ch + (size_t)m * N;
                #pragma unroll
                for (int bi = 0; bi < 2; bi++) {
                    int colblk = n0 + wn + bi * 32;
                    int part = colblk / DD;          // 0=q,1=k,2=v
                    if (part == 2) {
                        #pragma unroll
                        for (int pp = 0; pp < 4; pp++) {
                            int nt = bi * 4 + pp;
                            int n = n0 + wn + nt * 8 + 2 * u;
                            float c0 = acc[mt][nt][hf * 2    ] + bias[n];
                            float c1 = acc[mt][nt][hf * 2 + 1] + bias[n + 1];
                            *(__half2*)(crow + n) = __floats2half2_rn(c0, c1);
                        }
                    } else {
                        int axis = (colblk % DHH) >> 5;
                        float coord = cr[axis];
                        float sc = (part == 0) ? SCALE_Q : 1.0f;
                        #pragma unroll
                        for (int pp = 0; pp < 2; pp++) {
                            int nt1 = bi * 4 + pp, nt2 = nt1 + 2;
                            int n1 = n0 + wn + nt1 * 8 + 2 * u;
                            int n2 = n1 + 16;
                            int j0 = pp * 8 + 2 * u;
                            float ang0 = coord * ROPE_IF[j0];
                            float ang1 = coord * ROPE_IF[j0 + 1];
                            float sn0, cs0, sn1, cs1;
                            __sincosf(ang0, &sn0, &cs0);
                            __sincosf(ang1, &sn1, &cs1);
                            float x10 = acc[mt][nt1][hf * 2    ] + bias[n1];
                            float x11 = acc[mt][nt1][hf * 2 + 1] + bias[n1 + 1];
                            float x20 = acc[mt][nt2][hf * 2    ] + bias[n2];
                            float x21 = acc[mt][nt2][hf * 2 + 1] + bias[n2 + 1];
                            *(__half2*)(crow + n1) = __floats2half2_rn(
                                sc * (x10 * cs0 - x20 * sn0), sc * (x11 * cs1 - x21 * sn1));
                            *(__half2*)(crow + n2) = __floats2half2_rn(
                                sc * (x10 * sn0 + x20 * cs0), sc * (x11 * sn1 + x21 * cs1));
                        }
                    }
                }
            }
        }
    } else {
        #pragma unroll
        for (int mt = 0; mt < 2; mt++) {
            #pragma unroll
            for (int hf = 0; hf < 2; hf++) {
                int m = m0 + wm + mt * 16 + lane4 + hf * 8;
                #pragma unroll
                for (int nt = 0; nt < 8; nt++) {
                    int n = n0 + wn + nt * 8 + 2 * u;
                    float c0 = acc[mt][nt][hf * 2    ] + bias[n];
                    float c1 = acc[mt][nt][hf * 2 + 1] + bias[n + 1];
                    if (mode == 2) {
                        const float* rrow = res + (size_t)m * N;
                        float2 o;
                        o.x = c0 + rrow[n];
                        o.y = c1 + rrow[n + 1];
                        *(float2*)(Cf + (size_t)m * N + n) = o;   // STG.64
                    } else {
                        if (mode == 1) {
                            c0 = gelu_fast(c0);
                            c1 = gelu_fast(c1);
                        }
                        *(__half2*)(Ch + (size_t)m * N + n) = __floats2half2_rn(c0, c1);
                    }
                }
            }
        }
    }
}

// ---------------- fp16 tensor-core causal flash attention (R14 shape) -------
// 64 q-rows/block, 128 threads, kv tiles of 64, double-buffered K/V,
// exp2-domain softmax, ONE barrier per tile, conditional rescale.
__global__ __launch_bounds__(128) void attn_fp16() {
    extern __shared__ char sm[];
    const uint32_t base = smem_u32(sm);
    const int t = threadIdx.x, lane = t & 31, w = t >> 5;
    const int L = lane & 7, gb = (lane >> 3) & 1, gh = lane >> 4;
    const int lane4 = lane >> 2, u = lane & 3;
    const int qt = blockIdx.x;
    const int bh = blockIdx.y;
    const int b = bh >> 3, h = bh & 7;
    const __half* qkv = g_qkv + (size_t)b * SS * (3 * DD);

    uint32_t soff[6]; int rows[6], cks[6];
    #pragma unroll
    for (int it = 0; it < 6; it++) {
        int idx = t + 128 * it;
        int row = idx / 12, c = idx % 12;
        rows[it] = row; cks[it] = c;
        soff[it] = (uint32_t)row * 256u + ((uint32_t)((c & 8) | ((c ^ row) & 7)) << 4);
    }

    #pragma unroll
    for (int it = 0; it < 6; it++)
        cp_async16(base + soff[it], qkv + (size_t)(qt * 64 + rows[it]) * (3 * DD) + h * DHH + cks[it] * 8);
    cp_commit();
    asm volatile("cp.async.wait_group 0;" ::: "memory");
    __syncthreads();

    uint32_t qa[6][4];
    const uint32_t qRow = (uint32_t)(w * 16 + gb * 8 + L) * 256u;
    #pragma unroll
    for (int ks = 0; ks < 6; ks++) {
        int c = 2 * ks + gh;
        ldm_x4(qa[ks], base + qRow + ((uint32_t)((c & 8) | ((c ^ L) & 7)) << 4));
    }
    __syncthreads();

    float oacc[12][4];
    #pragma unroll
    for (int nt = 0; nt < 12; nt++)
        #pragma unroll
        for (int i = 0; i < 4; i++) oacc[nt][i] = 0.f;
    float m0 = -INFINITY, m1 = -INFINITY, l0 = 0.f, l1 = 0.f;

    uint32_t kRow[4];
    #pragma unroll
    for (int p = 0; p < 4; p++) kRow[p] = (uint32_t)(p * 16 + gh * 8 + L) * 256u;

    #pragma unroll
    for (int it = 0; it < 6; it++) {
        const __half* kp = qkv + (size_t)rows[it] * (3 * DD) + DD + h * DHH + cks[it] * 8;
        cp_async16(base + soff[it], kp);
        cp_async16(base + 32768u + soff[it], kp + DD);
    }
    cp_commit();

    for (int kt = 0; kt <= qt; kt++) {
        uint32_t buf = (uint32_t)(kt & 1) * 16384u;
        asm volatile("cp.async.wait_group 0;" ::: "memory");
        __syncthreads();

        if (kt < qt) {
            uint32_t nbuf = (uint32_t)((kt + 1) & 1) * 16384u;
            #pragma unroll
            for (int it = 0; it < 6; it++) {
                const __half* kp = qkv + (size_t)((kt + 1) * 64 + rows[it]) * (3 * DD) + DD + h * DHH + cks[it] * 8;
                cp_async16(base + nbuf + soff[it], kp);
                cp_async16(base + 32768u + nbuf + soff[it], kp + DD);
            }
            cp_commit();
        }

        const uint32_t kb = base + buf;
        const uint32_t vb = base + 32768u + buf;

        float sfr[8][4];
        #pragma unroll
        for (int nt = 0; nt < 8; nt++)
            #pragma unroll
            for (int i = 0; i < 4; i++) sfr[nt][i] = 0.f;
        #pragma unroll
        for (int ks = 0; ks < 6; ks++) {
            int c = 2 * ks + gb;
            uint32_t coff = (uint32_t)((c & 8) | ((c ^ L) & 7)) << 4;
            #pragma unroll
            for (int p = 0; p < 4; p++) {
                uint32_t bf[4];
                ldm_x4(bf, kb + kRow[p] + coff);
                mma16816(sfr[2 * p],     qa[ks], bf);
                mma16816(sfr[2 * p + 1], qa[ks], bf + 2);
            }
        }
        if (kt == qt) {
            int r0 = w * 16 + lane4, r1 = r0 + 8;
            #pragma unroll
            for (int nt = 0; nt < 8; nt++) {
                int ca = nt * 8 + 2 * u, cbn = ca + 1;
                if (ca  > r0) sfr[nt][0] = -1e30f;
                if (cbn > r0) sfr[nt][1] = -1e30f;
                if (ca  > r1) sfr[nt][2] = -1e30f;
                if (cbn > r1) sfr[nt][3] = -1e30f;
            }
        }
        float mx0 = -INFINITY, mx1 = -INFINITY;
        #pragma unroll
        for (int nt = 0; nt < 8; nt++) {
            mx0 = fmaxf(mx0, fmaxf(sfr[nt][0], sfr[nt][1]));
            mx1 = fmaxf(mx1, fmaxf(sfr[nt][2], sfr[nt][3]));
        }
        mx0 = fmaxf(mx0, __shfl_xor_sync(0xffffffffu, mx0, 1));
        mx0 = fmaxf(mx0, __shfl_xor_sync(0xffffffffu, mx0, 2));
        mx1 = fmaxf(mx1, __shfl_xor_sync(0xffffffffu, mx1, 1));
        mx1 = fmaxf(mx1, __shfl_xor_sync(0xffffffffu, mx1, 2));
        float mn0 = fmaxf(m0, mx0), mn1 = fmaxf(m1, mx1);
        if (mn0 > m0 || mn1 > m1) {
            float al0 = exp2f(m0 - mn0), al1 = exp2f(m1 - mn1);
            m0 = mn0; m1 = mn1;
            l0 *= al0; l1 *= al1;
            #pragma unroll
            for (int nt = 0; nt < 12; nt++) {
                oacc[nt][0] *= al0; oacc[nt][1] *= al0;
                oacc[nt][2] *= al1; oacc[nt][3] *= al1;
            }
        }
        #pragma unroll
        for (int nt = 0; nt < 8; nt++) {
            float p0 = exp2f(sfr[nt][0] - m0), p1 = exp2f(sfr[nt][1] - m0);
            float p2 = exp2f(sfr[nt][2] - m1), p3 = exp2f(sfr[nt][3] - m1);
            l0 += p0 + p1; l1 += p2 + p3;
            sfr[nt][0] = p0; sfr[nt][1] = p1; sfr[nt][2] = p2; sfr[nt][3] = p3;
        }
        #pragma unroll
        for (int j = 0; j < 4; j++) {
            uint32_t a[4];
            __half2 h0 = __floats2half2_rn(sfr[2*j][0],     sfr[2*j][1]);
            __half2 h1 = __floats2half2_rn(sfr[2*j][2],     sfr[2*j][3]);
            __half2 h2 = __floats2half2_rn(sfr[2*j + 1][0], sfr[2*j + 1][1]);
            __half2 h3 = __floats2half2_rn(sfr[2*j + 1][2], sfr[2*j + 1][3]);
            a[0] = *(uint32_t*)&h0; a[1] = *(uint32_t*)&h1;
            a[2] = *(uint32_t*)&h2; a[3] = *(uint32_t*)&h3;
            uint32_t rv = vb + (uint32_t)(j * 16 + L + gb * 8) * 256u;
            #pragma unroll
            for (int p = 0; p < 6; p++) {
                int c = 2 * p + gh;
                uint32_t bf[4];
                ldm_x4t(bf, rv + ((uint32_t)((c & 8) | ((c ^ L) & 7)) << 4));
                mma16816(oacc[2 * p],     a, bf);
                mma16816(oacc[2 * p + 1], a, bf + 2);
            }
        }
    }

    l0 += __shfl_xor_sync(0xffffffffu, l0, 1);
    l0 += __shfl_xor_sync(0xffffffffu, l0, 2);
    l1 += __shfl_xor_sync(0xffffffffu, l1, 1);
    l1 += __shfl_xor_sync(0xffffffffu, l1, 2);
    float i0 = 1.0f / l0, i1 = 1.0f / l1;
    int gr0 = qt * 64 + w * 16 + lane4, gr1 = gr0 + 8;
    __half* o0 = g_attn + (size_t)(b * SS + gr0) * DD + h * DHH;
    __half* o1 = g_attn + (size_t)(b * SS + gr1) * DD + h * DHH;
    #pragma unroll
    for (int nt = 0; nt < 12; nt++) {
        int c = nt * 8 + 2 * u;
        __half2 a0 = __floats2half2_rn(oacc[nt][0] * i0, oacc[nt][1] * i0);
        __half2 a1 = __floats2half2_rn(oacc[nt][2] * i1, oacc[nt][3] * i1);
        *(__half2*)(o0 + c) = a0;
        *(__half2*)(o1 + c) = a1;
    }
}

// ---------------- launch ----------------------------------------------------
extern "C" void kernel_launch(void* const* d_in, const int* in_sizes, int n_in,
                              void* d_out, int out_size) {
    const float* src     = (const float*)d_in[0];
    const float* coords  = (const float*)d_in[1];
    const float* norm1_g = (const float*)d_in[3];
    const float* norm1_b = (const float*)d_in[4];
    const float* qkv_w   = (const float*)d_in[5];
    const float* qkv_b   = (const float*)d_in[6];
    const float* proj_w  = (const float*)d_in[7];
    const float* proj_b  = (const float*)d_in[8];
    const float* norm2_g = (const float*)d_in[9];
    const float* norm2_b = (const float*)d_in[10];
    const float* fc1_w   = (const float*)d_in[11];
    const float* fc1_b   = (const float*)d_in[12];
    const float* fc2_w   = (const float*)d_in[13];
    const float* fc2_b   = (const float*)d_in[14];
    float* out = (float*)d_out;

    __half *xn, *qkvp, *attnp, *yp, *hp;
    __half *qkvw, *projw, *fc1w, *fc2w;
    float *x1p;
    cudaGetSymbolAddress((void**)&xn,    g_xn);
    cudaGetSymbolAddress((void**)&qkvp,  g_qkv);
    cudaGetSymbolAddress((void**)&attnp, g_attn);
    cudaGetSymbolAddress((void**)&x1p,   g_x1);
    cudaGetSymbolAddress((void**)&yp,    g_y);
    cudaGetSymbolAddress((void**)&hp,    g_h);
    cudaGetSymbolAddress((void**)&qkvw,  g_qkvw16);
    cudaGetSymbolAddress((void**)&projw, g_projw16);
    cudaGetSymbolAddress((void**)&fc1w,  g_fc1w16);
    cudaGetSymbolAddress((void**)&fc2w,  g_fc2w16);

    static bool attr_set = false;
    if (!attr_set) {
        cudaFuncSetAttribute(gemm_fp16, cudaFuncAttributeMaxDynamicSharedMemorySize, 98304);
        cudaFuncSetAttribute(attn_fp16, cudaFuncAttributeMaxDynamicSharedMemorySize, 65536);
        attr_set = true;
    }

    conv_ln<<<NCONV + BS, 256>>>(qkv_w, proj_w, fc1_w, fc2_w,
                                 src, norm1_g, norm1_b, xn);
    gemm_fp16<<<dim3((3*DD)/128, BS/128), 256, 98304>>>(
        xn, qkvw, qkv_b, nullptr, nullptr, qkvp, coords, BS, 3*DD, DD, 3);
    attn_fp16<<<dim3(SS / 64, BB * HH), 128, 65536>>>();
    gemm_fp16<<<dim3(DD/128, BS/128), 256, 98304>>>(
        attnp, projw, proj_b, src, x1p, nullptr, nullptr, BS, DD, DD, 2);
    ln_kernel<<<BS, 256>>>(x1p, norm2_g, norm2_b, yp);
    gemm_fp16<<<dim3(HID/128, BS/128), 256, 98304>>>(
        yp, fc1w, fc1_b, nullptr, nullptr, hp, nullptr, BS, HID, DD, 1);
    gemm_fp16<<<dim3(DD/128, BS/128), 256, 98304>>>(
        hp, fc2w, fc2_b, x1p, out, nullptr, nullptr, BS, DD, HID, 2);
}